// round 3
// baseline (speedup 1.0000x reference)
#include <cuda_runtime.h>
#include <math.h>

#define L_SEQ 2048
#define NB 2
#define DM 768
#define DI 1536
#define DS 16
#define DTR 48
#define NROWS (NB * L_SEQ)          // 4096
#define PROJW (DTR + 2 * DS)        // 80

// ---------------- scratch (static device globals, no allocation) ----------------
__device__ float g_h[(size_t)NROWS * DM];          // layernorm output
__device__ float g_xz[(size_t)NROWS * 2 * DI];     // input projection (xin | z)
__device__ float g_xc[(size_t)NROWS * DI];         // conv + silu output
__device__ float g_proj[(size_t)NROWS * PROJW];    // dt_raw | B | C
__device__ float g_dt[(size_t)NROWS * DI];         // softplus(dt)
__device__ float g_y[(size_t)NROWS * DI];          // scan output (gated)

// ---------------- LayerNorm ----------------
__global__ __launch_bounds__(256) void ln_kernel(const float* __restrict__ x,
                                                 const float* __restrict__ gamma,
                                                 const float* __restrict__ beta) {
    int row = blockIdx.x;
    const float* xr = x + (size_t)row * DM;
    float sum = 0.f, sq = 0.f;
    for (int i = threadIdx.x; i < DM; i += 256) {
        float v = xr[i];
        sum += v;
        sq  += v * v;
    }
    __shared__ float sh[2][8];
    #pragma unroll
    for (int o = 16; o; o >>= 1) {
        sum += __shfl_xor_sync(0xffffffffu, sum, o);
        sq  += __shfl_xor_sync(0xffffffffu, sq, o);
    }
    int w = threadIdx.x >> 5, lane = threadIdx.x & 31;
    if (lane == 0) { sh[0][w] = sum; sh[1][w] = sq; }
    __syncthreads();
    if (threadIdx.x < 32) {
        sum = (lane < 8) ? sh[0][lane] : 0.f;
        sq  = (lane < 8) ? sh[1][lane] : 0.f;
        #pragma unroll
        for (int o = 4; o; o >>= 1) {
            sum += __shfl_xor_sync(0xffffffffu, sum, o);
            sq  += __shfl_xor_sync(0xffffffffu, sq, o);
        }
        if (lane == 0) { sh[0][0] = sum; sh[1][0] = sq; }
    }
    __syncthreads();
    float mu  = sh[0][0] * (1.f / DM);
    float var = sh[1][0] * (1.f / DM) - mu * mu;
    float inv = rsqrtf(var + 1e-5f);
    for (int i = threadIdx.x; i < DM; i += 256)
        g_h[(size_t)row * DM + i] = (xr[i] - mu) * inv * gamma[i] + beta[i];
}

// ---------------- Generic tiled SGEMM  C[M,N] = A[M,K] @ B[K,N] (+epilogue) ----
// EPI: 0 = none, 1 = softplus(acc + bias[n]), 2 = acc + res[m,n]
// Assumes M % 128 == 0 and K % 8 == 0 (true for all call sites); N guarded.
template <int EPI>
__global__ __launch_bounds__(256) void sgemm(const float* __restrict__ A, int lda,
                                             const float* __restrict__ B, int ldb,
                                             float* __restrict__ C, int ldc,
                                             int M, int N, int K,
                                             const float* __restrict__ bias,
                                             const float* __restrict__ res, int ldres) {
    constexpr int BM = 128, BN = 128, BK = 8, TM = 8, TN = 8;
    __shared__ float As[BK][BM];
    __shared__ float Bs[BK][BN];

    int tid  = threadIdx.x;
    int trow = tid / 16, tcol = tid % 16;
    int arow = tid >> 1, acol0 = (tid & 1) * 4;
    int brow = tid >> 5, bcol0 = (tid & 31) * 4;

    const float* Ag = A + (size_t)(blockIdx.y * BM + arow) * lda + acol0;
    float acc[TM][TN] = {};

    for (int k0 = 0; k0 < K; k0 += BK) {
        float4 av = *reinterpret_cast<const float4*>(Ag + k0);
        As[acol0 + 0][arow] = av.x;
        As[acol0 + 1][arow] = av.y;
        As[acol0 + 2][arow] = av.z;
        As[acol0 + 3][arow] = av.w;

        int gbc = blockIdx.x * BN + bcol0;
        const float* Bp = B + (size_t)(k0 + brow) * ldb;
        float4 bv = make_float4(0.f, 0.f, 0.f, 0.f);
        if (gbc + 3 < N) {
            bv = *reinterpret_cast<const float4*>(Bp + gbc);
        } else {
            if (gbc + 0 < N) bv.x = Bp[gbc + 0];
            if (gbc + 1 < N) bv.y = Bp[gbc + 1];
            if (gbc + 2 < N) bv.z = Bp[gbc + 2];
            if (gbc + 3 < N) bv.w = Bp[gbc + 3];
        }
        *reinterpret_cast<float4*>(&Bs[brow][bcol0]) = bv;

        __syncthreads();
        #pragma unroll
        for (int kk = 0; kk < BK; kk++) {
            float a[TM], b[TN];
            #pragma unroll
            for (int i = 0; i < TM; i++) a[i] = As[kk][trow * TM + i];
            #pragma unroll
            for (int j = 0; j < TN; j++) b[j] = Bs[kk][tcol * TN + j];
            #pragma unroll
            for (int i = 0; i < TM; i++)
                #pragma unroll
                for (int j = 0; j < TN; j++)
                    acc[i][j] = fmaf(a[i], b[j], acc[i][j]);
        }
        __syncthreads();
    }

    #pragma unroll
    for (int i = 0; i < TM; i++) {
        int r = blockIdx.y * BM + trow * TM + i;
        #pragma unroll
        for (int j = 0; j < TN; j++) {
            int c = blockIdx.x * BN + tcol * TN + j;
            if (c < N) {
                float v = acc[i][j];
                if (EPI == 1) {
                    v += bias[c];
                    v = (v > 20.f) ? v : log1pf(__expf(v));
                }
                if (EPI == 2) {
                    v += res[(size_t)r * ldres + c];
                }
                C[(size_t)r * ldc + c] = v;
            }
        }
    }
}

// ---------------- Depthwise causal conv(4) + SiLU ----------------
__global__ __launch_bounds__(256) void conv_silu_kernel(const float* __restrict__ cw,
                                                        const float* __restrict__ cb) {
    int idx = blockIdx.x * blockDim.x + threadIdx.x;
    if (idx >= NROWS * DI) return;
    int d = idx % DI;
    int r = idx / DI;
    int l = r % L_SEQ;
    int b = r / L_SEQ;
    float acc = cb[d];
    #pragma unroll
    for (int k = 0; k < 4; k++) {
        int ll = l + k - 3;
        if (ll >= 0)
            acc = fmaf(g_xz[(size_t)(b * L_SEQ + ll) * (2 * DI) + d], cw[d * 4 + k], acc);
    }
    g_xc[idx] = acc / (1.f + __expf(-acc));   // silu
}

// ---------------- Selective scan: thread per (b, d, s), 16-lane reduce --------
// block = 256 threads = 16 channels x 16 states; grid = (DI/16, NB)
__global__ __launch_bounds__(256) void scan_kernel(const float* __restrict__ A_log,
                                                   const float* __restrict__ Dp) {
    int s    = threadIdx.x & 15;
    int dloc = threadIdx.x >> 4;
    int d    = blockIdx.x * 16 + dloc;
    int b    = blockIdx.y;

    float A  = -__expf(A_log[d * DS + s]);
    float Dv = Dp[d];
    float h  = 0.f;

    int row = b * L_SEQ;
    for (int l = 0; l < L_SEQ; l++, row++) {
        float dtv = g_dt[(size_t)row * DI + d];
        float xv  = g_xc[(size_t)row * DI + d];
        float Bv  = g_proj[(size_t)row * PROJW + DTR + s];
        float Cv  = g_proj[(size_t)row * PROJW + DTR + DS + s];

        h = fmaf(h, __expf(dtv * A), dtv * xv * Bv);
        float part = h * Cv;
        part += __shfl_xor_sync(0xffffffffu, part, 8);
        part += __shfl_xor_sync(0xffffffffu, part, 4);
        part += __shfl_xor_sync(0xffffffffu, part, 2);
        part += __shfl_xor_sync(0xffffffffu, part, 1);
        if (s == 0) {
            float zv  = g_xz[(size_t)row * (2 * DI) + DI + d];
            float sig = 1.f / (1.f + __expf(-zv));
            g_y[(size_t)row * DI + d] = (part + xv * Dv) * (zv * sig);
        }
    }
}

// ---------------- launch ----------------
extern "C" void kernel_launch(void* const* d_in, const int* in_sizes, int n_in,
                              void* d_out, int out_size) {
    const float* x      = (const float*)d_in[0];
    const float* gamma  = (const float*)d_in[1];
    const float* beta   = (const float*)d_in[2];
    const float* W_in   = (const float*)d_in[3];
    const float* conv_w = (const float*)d_in[4];
    const float* conv_b = (const float*)d_in[5];
    const float* W_x    = (const float*)d_in[6];
    const float* W_dt   = (const float*)d_in[7];
    const float* b_dt   = (const float*)d_in[8];
    const float* A_log  = (const float*)d_in[9];
    const float* Dp     = (const float*)d_in[10];
    const float* W_out  = (const float*)d_in[11];
    float* out = (float*)d_out;

    float *ph, *pxz, *pxc, *pproj, *pdt, *py;
    cudaGetSymbolAddress((void**)&ph,    g_h);
    cudaGetSymbolAddress((void**)&pxz,   g_xz);
    cudaGetSymbolAddress((void**)&pxc,   g_xc);
    cudaGetSymbolAddress((void**)&pproj, g_proj);
    cudaGetSymbolAddress((void**)&pdt,   g_dt);
    cudaGetSymbolAddress((void**)&py,    g_y);

    // 1. LayerNorm
    ln_kernel<<<NROWS, 256>>>(x, gamma, beta);

    // 2. xz = h @ W_in   [4096,768] x [768,3072]
    sgemm<0><<<dim3((2 * DI) / 128, NROWS / 128), 256>>>(
        ph, DM, W_in, 2 * DI, pxz, 2 * DI, NROWS, 2 * DI, DM, nullptr, nullptr, 0);

    // 3. depthwise conv + silu
    conv_silu_kernel<<<(NROWS * DI + 255) / 256, 256>>>(conv_w, conv_b);

    // 4. proj = xc @ W_x   [4096,1536] x [1536,80]
    sgemm<0><<<dim3(1, NROWS / 128), 256>>>(
        pxc, DI, W_x, PROJW, pproj, PROJW, NROWS, PROJW, DI, nullptr, nullptr, 0);

    // 5. dt = softplus(proj[:, :48] @ W_dt + b_dt)   [4096,48] x [48,1536]
    sgemm<1><<<dim3(DI / 128, NROWS / 128), 256>>>(
        pproj, PROJW, W_dt, DI, pdt, DI, NROWS, DI, DTR, b_dt, nullptr, 0);

    // 6. selective scan + D skip + silu(z) gate
    scan_kernel<<<dim3(DI / 16, NB), 256>>>(A_log, Dp);

    // 7. out = x + y @ W_out   [4096,1536] x [1536,768]
    sgemm<2><<<dim3(DM / 128, NROWS / 128), 256>>>(
        py, DI, W_out, DM, out, DM, NROWS, DM, DI, nullptr, x, DM);
}

// round 7
// speedup vs baseline: 1.4389x; 1.4389x over previous
#include <cuda_runtime.h>
#include <math.h>
#include <stdint.h>

#define L_SEQ 2048
#define NB 2
#define DM 768
#define DI 1536
#define DS 16
#define DTR 48
#define NROWS (NB * L_SEQ)          // 4096
#define PROJW (DTR + 2 * DS)        // 80

// ---------------- scratch (static device globals, no allocation) ----------------
__device__ float g_h[(size_t)NROWS * DM];
__device__ float g_xz[(size_t)NROWS * 2 * DI];
__device__ float g_xc[(size_t)NROWS * DI];
__device__ float g_proj[(size_t)NROWS * PROJW];
__device__ float g_dt[(size_t)NROWS * DI];
__device__ float g_y[(size_t)NROWS * DI];
// transposed weights (K-major B operands: Bt[n][k])
__device__ float g_WtIn[(size_t)(2 * DI) * DM];
__device__ float g_WtX[(size_t)PROJW * DI];
__device__ float g_WtDt[(size_t)DI * DTR];
__device__ float g_WtOut[(size_t)DM * DI];

__device__ __forceinline__ uint32_t smem_u32(const void* p) {
    uint32_t a;
    asm("{ .reg .u64 t; cvta.to.shared.u64 t, %1; cvt.u32.u64 %0, t; }" : "=r"(a) : "l"(p));
    return a;
}

// ---------------- LayerNorm ----------------
__global__ __launch_bounds__(256) void ln_kernel(const float* __restrict__ x,
                                                 const float* __restrict__ gamma,
                                                 const float* __restrict__ beta) {
    int row = blockIdx.x;
    const float* xr = x + (size_t)row * DM;
    float sum = 0.f, sq = 0.f;
    for (int i = threadIdx.x; i < DM; i += 256) {
        float v = xr[i];
        sum += v;
        sq  += v * v;
    }
    __shared__ float sh[2][8];
    #pragma unroll
    for (int o = 16; o; o >>= 1) {
        sum += __shfl_xor_sync(0xffffffffu, sum, o);
        sq  += __shfl_xor_sync(0xffffffffu, sq, o);
    }
    int w = threadIdx.x >> 5, lane = threadIdx.x & 31;
    if (lane == 0) { sh[0][w] = sum; sh[1][w] = sq; }
    __syncthreads();
    if (threadIdx.x < 32) {
        sum = (lane < 8) ? sh[0][lane] : 0.f;
        sq  = (lane < 8) ? sh[1][lane] : 0.f;
        #pragma unroll
        for (int o = 4; o; o >>= 1) {
            sum += __shfl_xor_sync(0xffffffffu, sum, o);
            sq  += __shfl_xor_sync(0xffffffffu, sq, o);
        }
        if (lane == 0) { sh[0][0] = sum; sh[1][0] = sq; }
    }
    __syncthreads();
    float mu  = sh[0][0] * (1.f / DM);
    float var = sh[1][0] * (1.f / DM) - mu * mu;
    float inv = rsqrtf(var + 1e-5f);
    for (int i = threadIdx.x; i < DM; i += 256)
        g_h[(size_t)row * DM + i] = (xr[i] - mu) * inv * gamma[i] + beta[i];
}

// ---------------- Transpose: out[c][r] = in[r][c], in is [R][C] ----------------
__global__ __launch_bounds__(256) void transpose_kernel(const float* __restrict__ in,
                                                        float* __restrict__ out,
                                                        int R, int C) {
    __shared__ float t[32][33];
    int c0 = blockIdx.x * 32, r0 = blockIdx.y * 32;
    #pragma unroll
    for (int i = 0; i < 32; i += 8) {
        int x = c0 + threadIdx.x, y = r0 + threadIdx.y + i;
        if (x < C && y < R) t[threadIdx.y + i][threadIdx.x] = in[(size_t)y * C + x];
    }
    __syncthreads();
    #pragma unroll
    for (int i = 0; i < 32; i += 8) {
        int x = r0 + threadIdx.x, y = c0 + threadIdx.y + i;
        if (x < R && y < C) out[(size_t)y * R + x] = t[threadIdx.x][threadIdx.y + i];
    }
}

// ---------------- tf32 mma.sync GEMM: C[M,N] = A[M,K] @ Bt[N,K]^T -------------
// CTA 128x128, BK=32 floats, double-buffered cp.async, 8 warps of 64x32 tiles.
// EPI: 0 none, 1 softplus(acc + bias[n]), 2 acc + res[m][n].
// Requires M%128==0, lda/ldb multiples of 4; N,K arbitrary (zfill tails, N%2==0).
#define GEMM_SMEM (2 * 4608 * 2 * 4)   // 73728 bytes
#define SPITCH 36                       // smem row pitch in floats (conflict-free)

template <int EPI>
__global__ __launch_bounds__(256) void mma_gemm(
    const float* __restrict__ A, int lda,
    const float* __restrict__ Bt, int ldb,
    float* __restrict__ C, int ldc,
    int N, int K,
    const float* __restrict__ bias,
    const float* __restrict__ res, int ldres)
{
    extern __shared__ float sm[];
    float* Asm = sm;                    // 2 buffers x 128 x SPITCH
    float* Bsm = sm + 2 * 128 * SPITCH;

    const int tid  = threadIdx.x;
    const int lane = tid & 31;
    const int wid  = tid >> 5;
    const int wm   = (wid & 1) * 64;    // warp m-offset in CTA tile
    const int wn   = (wid >> 1) * 32;   // warp n-offset
    const int m0   = blockIdx.y * 128;
    const int n0   = blockIdx.x * 128;

    float acc[4][4][4];
    #pragma unroll
    for (int i = 0; i < 4; i++)
        #pragma unroll
        for (int j = 0; j < 4; j++)
            #pragma unroll
            for (int q = 0; q < 4; q++) acc[i][j][q] = 0.f;

    const int NC = (K + 31) >> 5;

    auto load_chunk = [&](int c) {
        const int k0 = c << 5;
        int kw = K - k0; if (kw > 32) kw = 32;
        float* Ab = Asm + (c & 1) * 128 * SPITCH;
        float* Bb = Bsm + (c & 1) * 128 * SPITCH;
        #pragma unroll
        for (int it = 0; it < 4; ++it) {
            int v = tid + it * 256;     // 0..1023 float4 slots
            int r = v >> 3, s = v & 7;
            // A tile
            {
                int sz = (s * 4 < kw) ? 16 : 0;
                const float* src = sz ? (A + (size_t)(m0 + r) * lda + k0 + s * 4) : A;
                uint32_t dst = smem_u32(Ab + r * SPITCH + s * 4);
                asm volatile("cp.async.cg.shared.global [%0], [%1], 16, %2;"
                             :: "r"(dst), "l"(src), "r"(sz) : "memory");
            }
            // B tile (rows are output-n; zfill beyond N)
            {
                int n = n0 + r;
                int sz = (n < N && s * 4 < kw) ? 16 : 0;
                const float* src = sz ? (Bt + (size_t)n * ldb + k0 + s * 4) : Bt;
                uint32_t dst = smem_u32(Bb + r * SPITCH + s * 4);
                asm volatile("cp.async.cg.shared.global [%0], [%1], 16, %2;"
                             :: "r"(dst), "l"(src), "r"(sz) : "memory");
            }
        }
        asm volatile("cp.async.commit_group;" ::: "memory");
    };

    load_chunk(0);
    for (int c = 0; c < NC; ++c) {
        if (c + 1 < NC) {
            load_chunk(c + 1);
            asm volatile("cp.async.wait_group 1;" ::: "memory");
        } else {
            asm volatile("cp.async.wait_group 0;" ::: "memory");
        }
        __syncthreads();

        const float* Ab = Asm + (c & 1) * 128 * SPITCH;
        const float* Bb = Bsm + (c & 1) * 128 * SPITCH;
        const int ri = lane >> 2;
        #pragma unroll
        for (int kk = 0; kk < 4; ++kk) {
            const int kc = kk * 8 + (lane & 3);
            uint32_t af[4][4], bf[4][2];
            #pragma unroll
            for (int mi = 0; mi < 4; ++mi) {
                int r = wm + mi * 16 + ri;
                af[mi][0] = __float_as_uint(Ab[r * SPITCH + kc]);
                af[mi][1] = __float_as_uint(Ab[(r + 8) * SPITCH + kc]);
                af[mi][2] = __float_as_uint(Ab[r * SPITCH + kc + 4]);
                af[mi][3] = __float_as_uint(Ab[(r + 8) * SPITCH + kc + 4]);
            }
            #pragma unroll
            for (int ni = 0; ni < 4; ++ni) {
                int n = wn + ni * 8 + ri;
                bf[ni][0] = __float_as_uint(Bb[n * SPITCH + kc]);
                bf[ni][1] = __float_as_uint(Bb[n * SPITCH + kc + 4]);
            }
            #pragma unroll
            for (int mi = 0; mi < 4; ++mi)
                #pragma unroll
                for (int ni = 0; ni < 4; ++ni) {
                    asm volatile(
                        "mma.sync.aligned.m16n8k8.row.col.f32.tf32.tf32.f32 "
                        "{%0,%1,%2,%3}, {%4,%5,%6,%7}, {%8,%9}, {%0,%1,%2,%3};"
                        : "+f"(acc[mi][ni][0]), "+f"(acc[mi][ni][1]),
                          "+f"(acc[mi][ni][2]), "+f"(acc[mi][ni][3])
                        : "r"(af[mi][0]), "r"(af[mi][1]), "r"(af[mi][2]), "r"(af[mi][3]),
                          "r"(bf[ni][0]), "r"(bf[ni][1]));
                }
        }
        __syncthreads();
    }

    // ---- epilogue: fragment -> float2 STG ----
    #pragma unroll
    for (int mi = 0; mi < 4; ++mi) {
        #pragma unroll
        for (int ni = 0; ni < 4; ++ni) {
            int row = m0 + wm + mi * 16 + (lane >> 2);
            int col = n0 + wn + ni * 8 + 2 * (lane & 3);
            if (col < N) {
                #pragma unroll
                for (int h = 0; h < 2; ++h) {        // h=0: rows row, h=1: row+8
                    int r = row + h * 8;
                    float v0 = acc[mi][ni][h * 2 + 0];
                    float v1 = acc[mi][ni][h * 2 + 1];
                    if (EPI == 1) {
                        v0 += bias[col];
                        v1 += bias[col + 1];
                        v0 = (v0 > 20.f) ? v0 : log1pf(__expf(v0));
                        v1 = (v1 > 20.f) ? v1 : log1pf(__expf(v1));
                    }
                    if (EPI == 2) {
                        const float2 rr = *(const float2*)&res[(size_t)r * ldres + col];
                        v0 += rr.x; v1 += rr.y;
                    }
                    float2 o = make_float2(v0, v1);
                    *(float2*)&C[(size_t)r * ldc + col] = o;
                }
            }
        }
    }
}

// ---------------- Depthwise causal conv(4) + SiLU ----------------
__global__ __launch_bounds__(256) void conv_silu_kernel(const float* __restrict__ cw,
                                                        const float* __restrict__ cb) {
    int idx = blockIdx.x * blockDim.x + threadIdx.x;
    if (idx >= NROWS * DI) return;
    int d = idx % DI;
    int r = idx / DI;
    int l = r % L_SEQ;
    int b = r / L_SEQ;
    float acc = cb[d];
    #pragma unroll
    for (int k = 0; k < 4; k++) {
        int ll = l + k - 3;
        if (ll >= 0)
            acc = fmaf(g_xz[(size_t)(b * L_SEQ + ll) * (2 * DI) + d], cw[d * 4 + k], acc);
    }
    g_xc[idx] = acc / (1.f + __expf(-acc));
}

// ---------------- Selective scan ----------------
__global__ __launch_bounds__(256) void scan_kernel(const float* __restrict__ A_log,
                                                   const float* __restrict__ Dp) {
    int s    = threadIdx.x & 15;
    int dloc = threadIdx.x >> 4;
    int d    = blockIdx.x * 16 + dloc;
    int b    = blockIdx.y;

    float A  = -__expf(A_log[d * DS + s]);
    float Dv = Dp[d];
    float h  = 0.f;

    int row = b * L_SEQ;
    for (int l = 0; l < L_SEQ; l++, row++) {
        float dtv = g_dt[(size_t)row * DI + d];
        float xv  = g_xc[(size_t)row * DI + d];
        float Bv  = g_proj[(size_t)row * PROJW + DTR + s];
        float Cv  = g_proj[(size_t)row * PROJW + DTR + DS + s];

        h = fmaf(h, __expf(dtv * A), dtv * xv * Bv);
        float part = h * Cv;
        part += __shfl_xor_sync(0xffffffffu, part, 8);
        part += __shfl_xor_sync(0xffffffffu, part, 4);
        part += __shfl_xor_sync(0xffffffffu, part, 2);
        part += __shfl_xor_sync(0xffffffffu, part, 1);
        if (s == 0) {
            float zv  = g_xz[(size_t)row * (2 * DI) + DI + d];
            float sig = 1.f / (1.f + __expf(-zv));
            g_y[(size_t)row * DI + d] = (part + xv * Dv) * (zv * sig);
        }
    }
}

// ---------------- launch ----------------
extern "C" void kernel_launch(void* const* d_in, const int* in_sizes, int n_in,
                              void* d_out, int out_size) {
    const float* x      = (const float*)d_in[0];
    const float* gamma  = (const float*)d_in[1];
    const float* beta   = (const float*)d_in[2];
    const float* W_in   = (const float*)d_in[3];
    const float* conv_w = (const float*)d_in[4];
    const float* conv_b = (const float*)d_in[5];
    const float* W_x    = (const float*)d_in[6];
    const float* W_dt   = (const float*)d_in[7];
    const float* b_dt   = (const float*)d_in[8];
    const float* A_log  = (const float*)d_in[9];
    const float* Dp     = (const float*)d_in[10];
    const float* W_out  = (const float*)d_in[11];
    float* out = (float*)d_out;

    float *ph, *pxz, *pxc, *pproj, *pdt, *py;
    float *pWtIn, *pWtX, *pWtDt, *pWtOut;
    cudaGetSymbolAddress((void**)&ph,     g_h);
    cudaGetSymbolAddress((void**)&pxz,    g_xz);
    cudaGetSymbolAddress((void**)&pxc,    g_xc);
    cudaGetSymbolAddress((void**)&pproj,  g_proj);
    cudaGetSymbolAddress((void**)&pdt,    g_dt);
    cudaGetSymbolAddress((void**)&py,     g_y);
    cudaGetSymbolAddress((void**)&pWtIn,  g_WtIn);
    cudaGetSymbolAddress((void**)&pWtX,   g_WtX);
    cudaGetSymbolAddress((void**)&pWtDt,  g_WtDt);
    cudaGetSymbolAddress((void**)&pWtOut, g_WtOut);

    cudaFuncSetAttribute(mma_gemm<0>, cudaFuncAttributeMaxDynamicSharedMemorySize, GEMM_SMEM);
    cudaFuncSetAttribute(mma_gemm<1>, cudaFuncAttributeMaxDynamicSharedMemorySize, GEMM_SMEM);
    cudaFuncSetAttribute(mma_gemm<2>, cudaFuncAttributeMaxDynamicSharedMemorySize, GEMM_SMEM);

    dim3 tb(32, 8);
    transpose_kernel<<<dim3((2 * DI + 31) / 32, (DM + 31) / 32), tb>>>(W_in,  pWtIn,  DM, 2 * DI);
    transpose_kernel<<<dim3((PROJW + 31) / 32,  (DI + 31) / 32), tb>>>(W_x,   pWtX,   DI, PROJW);
    transpose_kernel<<<dim3((DI + 31) / 32,     (DTR + 31) / 32), tb>>>(W_dt, pWtDt,  DTR, DI);
    transpose_kernel<<<dim3((DM + 31) / 32,     (DI + 31) / 32), tb>>>(W_out, pWtOut, DI, DM);

    // 1. LayerNorm
    ln_kernel<<<NROWS, 256>>>(x, gamma, beta);

    // 2. xz = h @ W_in   [4096,768] x [768,3072]
    mma_gemm<0><<<dim3((2 * DI) / 128, NROWS / 128), 256, GEMM_SMEM>>>(
        ph, DM, pWtIn, DM, pxz, 2 * DI, 2 * DI, DM, nullptr, nullptr, 0);

    // 3. depthwise conv + silu
    conv_silu_kernel<<<(NROWS * DI + 255) / 256, 256>>>(conv_w, conv_b);

    // 4. proj = xc @ W_x   [4096,1536] x [1536,80]
    mma_gemm<0><<<dim3(1, NROWS / 128), 256, GEMM_SMEM>>>(
        pxc, DI, pWtX, DI, pproj, PROJW, PROJW, DI, nullptr, nullptr, 0);

    // 5. dt = softplus(proj[:, :48] @ W_dt + b_dt)   [4096,48] x [48,1536]
    mma_gemm<1><<<dim3(DI / 128, NROWS / 128), 256, GEMM_SMEM>>>(
        pproj, PROJW, pWtDt, DTR, pdt, DI, DI, DTR, b_dt, nullptr, 0);

    // 6. selective scan + D skip + silu(z) gate
    scan_kernel<<<dim3(DI / 16, NB), 256>>>(A_log, Dp);

    // 7. out = x + y @ W_out   [4096,1536] x [1536,768]
    mma_gemm<2><<<dim3(DM / 128, NROWS / 128), 256, GEMM_SMEM>>>(
        py, DI, pWtOut, DI, out, DM, DM, DI, nullptr, x, DM);
}

// round 10
// speedup vs baseline: 3.3753x; 2.3457x over previous
#include <cuda_runtime.h>
#include <math.h>
#include <stdint.h>

#define L_SEQ 2048
#define NB 2
#define DM 768
#define DI 1536
#define DS 16
#define DTR 48
#define NROWS (NB * L_SEQ)          // 4096
#define PROJW (DTR + 2 * DS)        // 80

// ---------------- scratch (static device globals, no allocation) ----------------
__device__ float g_h[(size_t)NROWS * DM];
__device__ float g_xz[(size_t)NROWS * 2 * DI];
__device__ float g_xc[(size_t)NROWS * DI];
__device__ float g_proj[(size_t)NROWS * PROJW];
__device__ float g_dt[(size_t)NROWS * DI];
__device__ float g_y[(size_t)NROWS * DI];
// transposed weights (K-major B operands: Bt[n][k])
__device__ float g_WtIn[(size_t)(2 * DI) * DM];
__device__ float g_WtX[(size_t)PROJW * DI];
__device__ float g_WtDt[(size_t)DI * DTR];
__device__ float g_WtOut[(size_t)DM * DI];

__device__ __forceinline__ uint32_t smem_u32(const void* p) {
    uint32_t a;
    asm("{ .reg .u64 t; cvta.to.shared.u64 t, %1; cvt.u32.u64 %0, t; }" : "=r"(a) : "l"(p));
    return a;
}

// ---------------- LayerNorm ----------------
__global__ __launch_bounds__(256) void ln_kernel(const float* __restrict__ x,
                                                 const float* __restrict__ gamma,
                                                 const float* __restrict__ beta) {
    int row = blockIdx.x;
    const float* xr = x + (size_t)row * DM;
    float sum = 0.f, sq = 0.f;
    for (int i = threadIdx.x; i < DM; i += 256) {
        float v = xr[i];
        sum += v;
        sq  += v * v;
    }
    __shared__ float sh[2][8];
    #pragma unroll
    for (int o = 16; o; o >>= 1) {
        sum += __shfl_xor_sync(0xffffffffu, sum, o);
        sq  += __shfl_xor_sync(0xffffffffu, sq, o);
    }
    int w = threadIdx.x >> 5, lane = threadIdx.x & 31;
    if (lane == 0) { sh[0][w] = sum; sh[1][w] = sq; }
    __syncthreads();
    if (threadIdx.x < 32) {
        sum = (lane < 8) ? sh[0][lane] : 0.f;
        sq  = (lane < 8) ? sh[1][lane] : 0.f;
        #pragma unroll
        for (int o = 4; o; o >>= 1) {
            sum += __shfl_xor_sync(0xffffffffu, sum, o);
            sq  += __shfl_xor_sync(0xffffffffu, sq, o);
        }
        if (lane == 0) { sh[0][0] = sum; sh[1][0] = sq; }
    }
    __syncthreads();
    float mu  = sh[0][0] * (1.f / DM);
    float var = sh[1][0] * (1.f / DM) - mu * mu;
    float inv = rsqrtf(var + 1e-5f);
    for (int i = threadIdx.x; i < DM; i += 256)
        g_h[(size_t)row * DM + i] = (xr[i] - mu) * inv * gamma[i] + beta[i];
}

// ---------------- Transpose tile body ----------------
__device__ __forceinline__ void transpose_tile(const float* __restrict__ in,
                                               float* __restrict__ out,
                                               int R, int C, int bx, int by) {
    __shared__ float t[32][33];
    int c0 = bx * 32, r0 = by * 32;
    #pragma unroll
    for (int i = 0; i < 32; i += 8) {
        int x = c0 + threadIdx.x, y = r0 + threadIdx.y + i;
        if (x < C && y < R) t[threadIdx.y + i][threadIdx.x] = in[(size_t)y * C + x];
    }
    __syncthreads();
    #pragma unroll
    for (int i = 0; i < 32; i += 8) {
        int x = r0 + threadIdx.x, y = c0 + threadIdx.y + i;
        if (x < R && y < C) out[(size_t)y * R + x] = t[threadIdx.x][threadIdx.y + i];
    }
}

__global__ __launch_bounds__(256) void transpose_win_kernel(const float* __restrict__ W_in) {
    // W_in [DM, 2*DI] -> g_WtIn [2*DI, DM]; grid.x = 96 (C tiles), grid.y = 24 (R tiles)
    transpose_tile(W_in, g_WtIn, DM, 2 * DI, blockIdx.x, blockIdx.y);
}

// Fused transpose of W_x, W_dt, W_out. 1D grid of 1392 tiles.
__global__ __launch_bounds__(256) void transpose_rest_kernel(const float* __restrict__ Wx,
                                                             const float* __restrict__ Wdt,
                                                             const float* __restrict__ Wout) {
    int t = blockIdx.x;
    if (t < 144) {              // W_x [DI, PROJW] -> g_WtX [PROJW, DI]
        transpose_tile(Wx, g_WtX, DI, PROJW, t % 3, t / 3);
    } else if (t < 240) {       // W_dt [DTR, DI] -> g_WtDt [DI, DTR]
        t -= 144;
        transpose_tile(Wdt, g_WtDt, DTR, DI, t % 48, t / 48);
    } else {                    // W_out [DI, DM] -> g_WtOut [DM, DI]
        t -= 240;
        transpose_tile(Wout, g_WtOut, DI, DM, t % 24, t / 24);
    }
}

// ---------------- tf32 mma.sync GEMM: C[M,N] = A[M,K] @ Bt[N,K]^T -------------
#define GEMM_SMEM (2 * 4608 * 2 * 4)   // 73728 bytes
#define SPITCH 36

template <int EPI>
__global__ __launch_bounds__(256) void mma_gemm(
    const float* __restrict__ A, int lda,
    const float* __restrict__ Bt, int ldb,
    float* __restrict__ C, int ldc,
    int N, int K,
    const float* __restrict__ bias,
    const float* __restrict__ res, int ldres)
{
    extern __shared__ float sm[];
    float* Asm = sm;
    float* Bsm = sm + 2 * 128 * SPITCH;

    const int tid  = threadIdx.x;
    const int lane = tid & 31;
    const int wid  = tid >> 5;
    const int wm   = (wid & 1) * 64;
    const int wn   = (wid >> 1) * 32;
    const int m0   = blockIdx.y * 128;
    const int n0   = blockIdx.x * 128;

    float acc[4][4][4];
    #pragma unroll
    for (int i = 0; i < 4; i++)
        #pragma unroll
        for (int j = 0; j < 4; j++)
            #pragma unroll
            for (int q = 0; q < 4; q++) acc[i][j][q] = 0.f;

    const int NC = (K + 31) >> 5;

    auto load_chunk = [&](int c) {
        const int k0 = c << 5;
        int kw = K - k0; if (kw > 32) kw = 32;
        float* Ab = Asm + (c & 1) * 128 * SPITCH;
        float* Bb = Bsm + (c & 1) * 128 * SPITCH;
        #pragma unroll
        for (int it = 0; it < 4; ++it) {
            int v = tid + it * 256;
            int r = v >> 3, s = v & 7;
            {
                int sz = (s * 4 < kw) ? 16 : 0;
                const float* src = sz ? (A + (size_t)(m0 + r) * lda + k0 + s * 4) : A;
                uint32_t dst = smem_u32(Ab + r * SPITCH + s * 4);
                asm volatile("cp.async.cg.shared.global [%0], [%1], 16, %2;"
                             :: "r"(dst), "l"(src), "r"(sz) : "memory");
            }
            {
                int n = n0 + r;
                int sz = (n < N && s * 4 < kw) ? 16 : 0;
                const float* src = sz ? (Bt + (size_t)n * ldb + k0 + s * 4) : Bt;
                uint32_t dst = smem_u32(Bb + r * SPITCH + s * 4);
                asm volatile("cp.async.cg.shared.global [%0], [%1], 16, %2;"
                             :: "r"(dst), "l"(src), "r"(sz) : "memory");
            }
        }
        asm volatile("cp.async.commit_group;" ::: "memory");
    };

    load_chunk(0);
    for (int c = 0; c < NC; ++c) {
        if (c + 1 < NC) {
            load_chunk(c + 1);
            asm volatile("cp.async.wait_group 1;" ::: "memory");
        } else {
            asm volatile("cp.async.wait_group 0;" ::: "memory");
        }
        __syncthreads();

        const float* Ab = Asm + (c & 1) * 128 * SPITCH;
        const float* Bb = Bsm + (c & 1) * 128 * SPITCH;
        const int ri = lane >> 2;
        #pragma unroll
        for (int kk = 0; kk < 4; ++kk) {
            const int kc = kk * 8 + (lane & 3);
            uint32_t af[4][4], bf[4][2];
            #pragma unroll
            for (int mi = 0; mi < 4; ++mi) {
                int r = wm + mi * 16 + ri;
                af[mi][0] = __float_as_uint(Ab[r * SPITCH + kc]);
                af[mi][1] = __float_as_uint(Ab[(r + 8) * SPITCH + kc]);
                af[mi][2] = __float_as_uint(Ab[r * SPITCH + kc + 4]);
                af[mi][3] = __float_as_uint(Ab[(r + 8) * SPITCH + kc + 4]);
            }
            #pragma unroll
            for (int ni = 0; ni < 4; ++ni) {
                int n = wn + ni * 8 + ri;
                bf[ni][0] = __float_as_uint(Bb[n * SPITCH + kc]);
                bf[ni][1] = __float_as_uint(Bb[n * SPITCH + kc + 4]);
            }
            #pragma unroll
            for (int mi = 0; mi < 4; ++mi)
                #pragma unroll
                for (int ni = 0; ni < 4; ++ni) {
                    asm volatile(
                        "mma.sync.aligned.m16n8k8.row.col.f32.tf32.tf32.f32 "
                        "{%0,%1,%2,%3}, {%4,%5,%6,%7}, {%8,%9}, {%0,%1,%2,%3};"
                        : "+f"(acc[mi][ni][0]), "+f"(acc[mi][ni][1]),
                          "+f"(acc[mi][ni][2]), "+f"(acc[mi][ni][3])
                        : "r"(af[mi][0]), "r"(af[mi][1]), "r"(af[mi][2]), "r"(af[mi][3]),
                          "r"(bf[ni][0]), "r"(bf[ni][1]));
                }
        }
        __syncthreads();
    }

    #pragma unroll
    for (int mi = 0; mi < 4; ++mi) {
        #pragma unroll
        for (int ni = 0; ni < 4; ++ni) {
            int row = m0 + wm + mi * 16 + (lane >> 2);
            int col = n0 + wn + ni * 8 + 2 * (lane & 3);
            if (col < N) {
                #pragma unroll
                for (int h = 0; h < 2; ++h) {
                    int r = row + h * 8;
                    float v0 = acc[mi][ni][h * 2 + 0];
                    float v1 = acc[mi][ni][h * 2 + 1];
                    if (EPI == 1) {
                        v0 += bias[col];
                        v1 += bias[col + 1];
                        v0 = (v0 > 20.f) ? v0 : log1pf(__expf(v0));
                        v1 = (v1 > 20.f) ? v1 : log1pf(__expf(v1));
                    }
                    if (EPI == 2) {
                        const float2 rr = *(const float2*)&res[(size_t)r * ldres + col];
                        v0 += rr.x; v1 += rr.y;
                    }
                    float2 o = make_float2(v0, v1);
                    *(float2*)&C[(size_t)r * ldc + col] = o;
                }
            }
        }
    }
}

// ---------------- Depthwise causal conv(4) + SiLU ----------------
__global__ __launch_bounds__(256) void conv_silu_kernel(const float* __restrict__ cw,
                                                        const float* __restrict__ cb) {
    int idx = blockIdx.x * blockDim.x + threadIdx.x;
    if (idx >= NROWS * DI) return;
    int d = idx % DI;
    int r = idx / DI;
    int l = r % L_SEQ;
    int b = r / L_SEQ;
    float acc = cb[d];
    #pragma unroll
    for (int k = 0; k < 4; k++) {
        int ll = l + k - 3;
        if (ll >= 0)
            acc = fmaf(g_xz[(size_t)(b * L_SEQ + ll) * (2 * DI) + d], cw[d * 4 + k], acc);
    }
    g_xc[idx] = acc / (1.f + __expf(-acc));
}

// ---------------- Selective scan (software-pipelined, U=8 load batches) -------
#define SCAN_U 8
__global__ __launch_bounds__(256) void scan_kernel(const float* __restrict__ A_log,
                                                   const float* __restrict__ Dp) {
    int s    = threadIdx.x & 15;
    int dloc = threadIdx.x >> 4;
    int d    = blockIdx.x * 16 + dloc;
    int b    = blockIdx.y;

    float A  = -__expf(A_log[d * DS + s]);
    float Dv = Dp[d];
    float h  = 0.f;

    const float* pdt = g_dt   + (size_t)(b * L_SEQ) * DI + d;
    const float* pxc = g_xc   + (size_t)(b * L_SEQ) * DI + d;
    const float* pz  = g_xz   + (size_t)(b * L_SEQ) * (2 * DI) + DI + d;
    const float* pB  = g_proj + (size_t)(b * L_SEQ) * PROJW + DTR + s;
    const float* pC  = pB + DS;
    float*       py  = g_y    + (size_t)(b * L_SEQ) * DI + d;

    for (int l0 = 0; l0 < L_SEQ; l0 += SCAN_U) {
        float dtv[SCAN_U], xv[SCAN_U], Bv[SCAN_U], Cv[SCAN_U], zv[SCAN_U];
        #pragma unroll
        for (int u = 0; u < SCAN_U; ++u) {
            int l = l0 + u;
            dtv[u] = __ldg(pdt + (size_t)l * DI);
            xv[u]  = __ldg(pxc + (size_t)l * DI);
            Bv[u]  = __ldg(pB  + (size_t)l * PROJW);
            Cv[u]  = __ldg(pC  + (size_t)l * PROJW);
            zv[u]  = __ldg(pz  + (size_t)l * (2 * DI));
        }
        #pragma unroll
        for (int u = 0; u < SCAN_U; ++u) {
            h = fmaf(h, __expf(dtv[u] * A), dtv[u] * xv[u] * Bv[u]);
            float part = h * Cv[u];
            part += __shfl_xor_sync(0xffffffffu, part, 8);
            part += __shfl_xor_sync(0xffffffffu, part, 4);
            part += __shfl_xor_sync(0xffffffffu, part, 2);
            part += __shfl_xor_sync(0xffffffffu, part, 1);
            if (s == 0) {
                float sig = 1.f / (1.f + __expf(-zv[u]));
                py[(size_t)(l0 + u) * DI] = (part + xv[u] * Dv) * (zv[u] * sig);
            }
        }
    }
}

// ---------------- launch ----------------
extern "C" void kernel_launch(void* const* d_in, const int* in_sizes, int n_in,
                              void* d_out, int out_size) {
    const float* x      = (const float*)d_in[0];
    const float* gamma  = (const float*)d_in[1];
    const float* beta   = (const float*)d_in[2];
    const float* W_in   = (const float*)d_in[3];
    const float* conv_w = (const float*)d_in[4];
    const float* conv_b = (const float*)d_in[5];
    const float* W_x    = (const float*)d_in[6];
    const float* W_dt   = (const float*)d_in[7];
    const float* b_dt   = (const float*)d_in[8];
    const float* A_log  = (const float*)d_in[9];
    const float* Dp     = (const float*)d_in[10];
    const float* W_out  = (const float*)d_in[11];
    float* out = (float*)d_out;

    float *ph, *pxz, *pxc, *pproj, *pdt, *py;
    float *pWtIn, *pWtX, *pWtDt, *pWtOut;
    cudaGetSymbolAddress((void**)&ph,     g_h);
    cudaGetSymbolAddress((void**)&pxz,    g_xz);
    cudaGetSymbolAddress((void**)&pxc,    g_xc);
    cudaGetSymbolAddress((void**)&pproj,  g_proj);
    cudaGetSymbolAddress((void**)&pdt,    g_dt);
    cudaGetSymbolAddress((void**)&py,     g_y);
    cudaGetSymbolAddress((void**)&pWtIn,  g_WtIn);
    cudaGetSymbolAddress((void**)&pWtX,   g_WtX);
    cudaGetSymbolAddress((void**)&pWtDt,  g_WtDt);
    cudaGetSymbolAddress((void**)&pWtOut, g_WtOut);

    cudaFuncSetAttribute(mma_gemm<0>, cudaFuncAttributeMaxDynamicSharedMemorySize, GEMM_SMEM);
    cudaFuncSetAttribute(mma_gemm<1>, cudaFuncAttributeMaxDynamicSharedMemorySize, GEMM_SMEM);
    cudaFuncSetAttribute(mma_gemm<2>, cudaFuncAttributeMaxDynamicSharedMemorySize, GEMM_SMEM);

    dim3 tb(32, 8);

    // launch 0: transpose W_in
    transpose_win_kernel<<<dim3(96, 24), tb>>>(W_in);
    // launch 1: LayerNorm
    ln_kernel<<<NROWS, 256>>>(x, gamma, beta);
    // launch 2: remaining transposes (fused)
    transpose_rest_kernel<<<1392, tb>>>(W_x, W_dt, W_out);

    // launch 3 (ncu capture slot): xz = h @ W_in   [4096,768] x [768,3072]
    mma_gemm<0><<<dim3((2 * DI) / 128, NROWS / 128), 256, GEMM_SMEM>>>(
        ph, DM, pWtIn, DM, pxz, 2 * DI, 2 * DI, DM, nullptr, nullptr, 0);

    // launch 4: depthwise conv + silu
    conv_silu_kernel<<<(NROWS * DI + 255) / 256, 256>>>(conv_w, conv_b);

    // launch 5: proj = xc @ W_x   [4096,1536] x [1536,80]
    mma_gemm<0><<<dim3(1, NROWS / 128), 256, GEMM_SMEM>>>(
        pxc, DI, pWtX, DI, pproj, PROJW, PROJW, DI, nullptr, nullptr, 0);

    // launch 6: dt = softplus(proj[:, :48] @ W_dt + b_dt)
    mma_gemm<1><<<dim3(DI / 128, NROWS / 128), 256, GEMM_SMEM>>>(
        pproj, PROJW, pWtDt, DTR, pdt, DI, DI, DTR, b_dt, nullptr, 0);

    // launch 7: selective scan + D skip + silu(z) gate
    scan_kernel<<<dim3(DI / 16, NB), 256>>>(A_log, Dp);

    // launch 8: out = x + y @ W_out   [4096,1536] x [1536,768]
    mma_gemm<2><<<dim3(DM / 128, NROWS / 128), 256, GEMM_SMEM>>>(
        py, DI, pWtOut, DI, out, DM, DM, DI, nullptr, x, DM);
}

// round 13
// speedup vs baseline: 3.5518x; 1.0523x over previous
#include <cuda_runtime.h>
#include <math.h>
#include <stdint.h>

#define L_SEQ 2048
#define NB 2
#define DM 768
#define DI 1536
#define DS 16
#define DTR 48
#define NROWS (NB * L_SEQ)          // 4096
#define PROJW (DTR + 2 * DS)        // 80

// ---------------- scratch (static device globals, no allocation) ----------------
__device__ float g_h[(size_t)NROWS * DM];
__device__ float g_xz[(size_t)NROWS * 2 * DI];
__device__ float g_xc[(size_t)NROWS * DI];
__device__ float g_proj[(size_t)NROWS * PROJW];
__device__ float g_dt[(size_t)NROWS * DI];
__device__ float g_y[(size_t)NROWS * DI];
// transposed weights (K-major B operands: Bt[n][k])
__device__ float g_WtIn[(size_t)(2 * DI) * DM];
__device__ float g_WtX[(size_t)PROJW * DI];
__device__ float g_WtDt[(size_t)DI * DTR];
__device__ float g_WtOut[(size_t)DM * DI];

__device__ __forceinline__ uint32_t smem_u32(const void* p) {
    uint32_t a;
    asm("{ .reg .u64 t; cvta.to.shared.u64 t, %1; cvt.u32.u64 %0, t; }" : "=r"(a) : "l"(p));
    return a;
}

// ---------------- LayerNorm ----------------
__global__ __launch_bounds__(256) void ln_kernel(const float* __restrict__ x,
                                                 const float* __restrict__ gamma,
                                                 const float* __restrict__ beta) {
    int row = blockIdx.x;
    const float* xr = x + (size_t)row * DM;
    float sum = 0.f, sq = 0.f;
    for (int i = threadIdx.x; i < DM; i += 256) {
        float v = xr[i];
        sum += v;
        sq  += v * v;
    }
    __shared__ float sh[2][8];
    #pragma unroll
    for (int o = 16; o; o >>= 1) {
        sum += __shfl_xor_sync(0xffffffffu, sum, o);
        sq  += __shfl_xor_sync(0xffffffffu, sq, o);
    }
    int w = threadIdx.x >> 5, lane = threadIdx.x & 31;
    if (lane == 0) { sh[0][w] = sum; sh[1][w] = sq; }
    __syncthreads();
    if (threadIdx.x < 32) {
        sum = (lane < 8) ? sh[0][lane] : 0.f;
        sq  = (lane < 8) ? sh[1][lane] : 0.f;
        #pragma unroll
        for (int o = 4; o; o >>= 1) {
            sum += __shfl_xor_sync(0xffffffffu, sum, o);
            sq  += __shfl_xor_sync(0xffffffffu, sq, o);
        }
        if (lane == 0) { sh[0][0] = sum; sh[1][0] = sq; }
    }
    __syncthreads();
    float mu  = sh[0][0] * (1.f / DM);
    float var = sh[1][0] * (1.f / DM) - mu * mu;
    float inv = rsqrtf(var + 1e-5f);
    for (int i = threadIdx.x; i < DM; i += 256)
        g_h[(size_t)row * DM + i] = (xr[i] - mu) * inv * gamma[i] + beta[i];
}

// ---------------- Transpose tile body ----------------
__device__ __forceinline__ void transpose_tile(const float* __restrict__ in,
                                               float* __restrict__ out,
                                               int R, int C, int bx, int by) {
    __shared__ float t[32][33];
    int c0 = bx * 32, r0 = by * 32;
    #pragma unroll
    for (int i = 0; i < 32; i += 8) {
        int x = c0 + threadIdx.x, y = r0 + threadIdx.y + i;
        if (x < C && y < R) t[threadIdx.y + i][threadIdx.x] = in[(size_t)y * C + x];
    }
    __syncthreads();
    #pragma unroll
    for (int i = 0; i < 32; i += 8) {
        int x = r0 + threadIdx.x, y = c0 + threadIdx.y + i;
        if (x < R && y < C) out[(size_t)y * R + x] = t[threadIdx.x][threadIdx.y + i];
    }
}

__global__ __launch_bounds__(256) void transpose_win_kernel(const float* __restrict__ W_in) {
    transpose_tile(W_in, g_WtIn, DM, 2 * DI, blockIdx.x, blockIdx.y);
}

__global__ __launch_bounds__(256) void transpose_rest_kernel(const float* __restrict__ Wx,
                                                             const float* __restrict__ Wdt,
                                                             const float* __restrict__ Wout) {
    int t = blockIdx.x;
    if (t < 144) {
        transpose_tile(Wx, g_WtX, DI, PROJW, t % 3, t / 3);
    } else if (t < 240) {
        t -= 144;
        transpose_tile(Wdt, g_WtDt, DTR, DI, t % 48, t / 48);
    } else {
        t -= 240;
        transpose_tile(Wout, g_WtOut, DI, DM, t % 24, t / 24);
    }
}

// ---------------- tf32 mma.sync GEMM: C[M,N] = A[M,K] @ Bt[N,K]^T -------------
#define GEMM_SMEM (2 * 4608 * 2 * 4)   // 73728 bytes
#define SPITCH 36

template <int EPI>
__global__ __launch_bounds__(256, 2) void mma_gemm(
    const float* __restrict__ A, int lda,
    const float* __restrict__ Bt, int ldb,
    float* __restrict__ C, int ldc,
    int N, int K,
    const float* __restrict__ bias,
    const float* __restrict__ res, int ldres)
{
    extern __shared__ float sm[];
    float* Asm = sm;
    float* Bsm = sm + 2 * 128 * SPITCH;

    const int tid  = threadIdx.x;
    const int lane = tid & 31;
    const int wid  = tid >> 5;
    const int wm   = (wid & 1) * 64;
    const int wn   = (wid >> 1) * 32;
    const int m0   = blockIdx.y * 128;
    const int n0   = blockIdx.x * 128;

    float acc[4][4][4];
    #pragma unroll
    for (int i = 0; i < 4; i++)
        #pragma unroll
        for (int j = 0; j < 4; j++)
            #pragma unroll
            for (int q = 0; q < 4; q++) acc[i][j][q] = 0.f;

    const int NC = (K + 31) >> 5;

    auto load_chunk = [&](int c) {
        const int k0 = c << 5;
        int kw = K - k0; if (kw > 32) kw = 32;
        float* Ab = Asm + (c & 1) * 128 * SPITCH;
        float* Bb = Bsm + (c & 1) * 128 * SPITCH;
        #pragma unroll
        for (int it = 0; it < 4; ++it) {
            int v = tid + it * 256;
            int r = v >> 3, s = v & 7;
            {
                int sz = (s * 4 < kw) ? 16 : 0;
                const float* src = sz ? (A + (size_t)(m0 + r) * lda + k0 + s * 4) : A;
                uint32_t dst = smem_u32(Ab + r * SPITCH + s * 4);
                asm volatile("cp.async.cg.shared.global [%0], [%1], 16, %2;"
                             :: "r"(dst), "l"(src), "r"(sz) : "memory");
            }
            {
                int n = n0 + r;
                int sz = (n < N && s * 4 < kw) ? 16 : 0;
                const float* src = sz ? (Bt + (size_t)n * ldb + k0 + s * 4) : Bt;
                uint32_t dst = smem_u32(Bb + r * SPITCH + s * 4);
                asm volatile("cp.async.cg.shared.global [%0], [%1], 16, %2;"
                             :: "r"(dst), "l"(src), "r"(sz) : "memory");
            }
        }
        asm volatile("cp.async.commit_group;" ::: "memory");
    };

    load_chunk(0);
    for (int c = 0; c < NC; ++c) {
        if (c + 1 < NC) {
            load_chunk(c + 1);
            asm volatile("cp.async.wait_group 1;" ::: "memory");
        } else {
            asm volatile("cp.async.wait_group 0;" ::: "memory");
        }
        __syncthreads();

        const float* Ab = Asm + (c & 1) * 128 * SPITCH;
        const float* Bb = Bsm + (c & 1) * 128 * SPITCH;
        const int ri = lane >> 2;
        #pragma unroll
        for (int kk = 0; kk < 4; ++kk) {
            const int kc = kk * 8 + (lane & 3);
            uint32_t af[4][4], bf[4][2];
            #pragma unroll
            for (int mi = 0; mi < 4; ++mi) {
                int r = wm + mi * 16 + ri;
                af[mi][0] = __float_as_uint(Ab[r * SPITCH + kc]);
                af[mi][1] = __float_as_uint(Ab[(r + 8) * SPITCH + kc]);
                af[mi][2] = __float_as_uint(Ab[r * SPITCH + kc + 4]);
                af[mi][3] = __float_as_uint(Ab[(r + 8) * SPITCH + kc + 4]);
            }
            #pragma unroll
            for (int ni = 0; ni < 4; ++ni) {
                int n = wn + ni * 8 + ri;
                bf[ni][0] = __float_as_uint(Bb[n * SPITCH + kc]);
                bf[ni][1] = __float_as_uint(Bb[n * SPITCH + kc + 4]);
            }
            #pragma unroll
            for (int mi = 0; mi < 4; ++mi)
                #pragma unroll
                for (int ni = 0; ni < 4; ++ni) {
                    asm volatile(
                        "mma.sync.aligned.m16n8k8.row.col.f32.tf32.tf32.f32 "
                        "{%0,%1,%2,%3}, {%4,%5,%6,%7}, {%8,%9}, {%0,%1,%2,%3};"
                        : "+f"(acc[mi][ni][0]), "+f"(acc[mi][ni][1]),
                          "+f"(acc[mi][ni][2]), "+f"(acc[mi][ni][3])
                        : "r"(af[mi][0]), "r"(af[mi][1]), "r"(af[mi][2]), "r"(af[mi][3]),
                          "r"(bf[ni][0]), "r"(bf[ni][1]));
                }
        }
        __syncthreads();
    }

    #pragma unroll
    for (int mi = 0; mi < 4; ++mi) {
        #pragma unroll
        for (int ni = 0; ni < 4; ++ni) {
            int row = m0 + wm + mi * 16 + (lane >> 2);
            int col = n0 + wn + ni * 8 + 2 * (lane & 3);
            if (col < N) {
                #pragma unroll
                for (int h = 0; h < 2; ++h) {
                    int r = row + h * 8;
                    float v0 = acc[mi][ni][h * 2 + 0];
                    float v1 = acc[mi][ni][h * 2 + 1];
                    if (EPI == 1) {
                        v0 += bias[col];
                        v1 += bias[col + 1];
                        v0 = (v0 > 20.f) ? v0 : log1pf(__expf(v0));
                        v1 = (v1 > 20.f) ? v1 : log1pf(__expf(v1));
                    }
                    if (EPI == 2) {
                        const float2 rr = *(const float2*)&res[(size_t)r * ldres + col];
                        v0 += rr.x; v1 += rr.y;
                    }
                    float2 o = make_float2(v0, v1);
                    *(float2*)&C[(size_t)r * ldc + col] = o;
                }
            }
        }
    }
}

// ---------------- Depthwise causal conv(4) + SiLU ----------------
__global__ __launch_bounds__(256) void conv_silu_kernel(const float* __restrict__ cw,
                                                        const float* __restrict__ cb) {
    int idx = blockIdx.x * blockDim.x + threadIdx.x;
    if (idx >= NROWS * DI) return;
    int d = idx % DI;
    int r = idx / DI;
    int l = r % L_SEQ;
    int b = r / L_SEQ;
    float acc = cb[d];
    #pragma unroll
    for (int k = 0; k < 4; k++) {
        int ll = l + k - 3;
        if (ll >= 0)
            acc = fmaf(g_xz[(size_t)(b * L_SEQ + ll) * (2 * DI) + d], cw[d * 4 + k], acc);
    }
    g_xc[idx] = acc / (1.f + __expf(-acc));
}

// ---------------- Selective scan (pipelined, exp hoisted off critical path) ---
#define SCAN_U 8
__global__ __launch_bounds__(256) void scan_kernel(const float* __restrict__ A_log,
                                                   const float* __restrict__ Dp) {
    int s    = threadIdx.x & 15;
    int dloc = threadIdx.x >> 4;
    int d    = blockIdx.x * 16 + dloc;
    int b    = blockIdx.y;

    float A  = -__expf(A_log[d * DS + s]);
    float Dv = Dp[d];
    float h  = 0.f;

    const float* pdt = g_dt   + (size_t)(b * L_SEQ) * DI + d;
    const float* pxc = g_xc   + (size_t)(b * L_SEQ) * DI + d;
    const float* pz  = g_xz   + (size_t)(b * L_SEQ) * (2 * DI) + DI + d;
    const float* pB  = g_proj + (size_t)(b * L_SEQ) * PROJW + DTR + s;
    const float* pC  = pB + DS;
    float*       py  = g_y    + (size_t)(b * L_SEQ) * DI + d;

    for (int l0 = 0; l0 < L_SEQ; l0 += SCAN_U) {
        float dA[SCAN_U], bx[SCAN_U], Cv[SCAN_U], zv[SCAN_U], xv[SCAN_U];
        #pragma unroll
        for (int u = 0; u < SCAN_U; ++u) {
            int l = l0 + u;
            float dtv = __ldg(pdt + (size_t)l * DI);
            xv[u]  = __ldg(pxc + (size_t)l * DI);
            float Bv = __ldg(pB  + (size_t)l * PROJW);
            Cv[u]  = __ldg(pC  + (size_t)l * PROJW);
            zv[u]  = __ldg(pz  + (size_t)l * (2 * DI));
            dA[u]  = __expf(dtv * A);          // off the serial chain
            bx[u]  = dtv * xv[u] * Bv;
        }
        #pragma unroll
        for (int u = 0; u < SCAN_U; ++u) {
            h = fmaf(h, dA[u], bx[u]);         // pure FMA recurrence
            float part = h * Cv[u];
            part += __shfl_xor_sync(0xffffffffu, part, 8);
            part += __shfl_xor_sync(0xffffffffu, part, 4);
            part += __shfl_xor_sync(0xffffffffu, part, 2);
            part += __shfl_xor_sync(0xffffffffu, part, 1);
            if (s == 0) {
                float sig = 1.f / (1.f + __expf(-zv[u]));
                py[(size_t)(l0 + u) * DI] = (part + xv[u] * Dv) * (zv[u] * sig);
            }
        }
    }
}

// ---------------- launch ----------------
extern "C" void kernel_launch(void* const* d_in, const int* in_sizes, int n_in,
                              void* d_out, int out_size) {
    const float* x      = (const float*)d_in[0];
    const float* gamma  = (const float*)d_in[1];
    const float* beta   = (const float*)d_in[2];
    const float* W_in   = (const float*)d_in[3];
    const float* conv_w = (const float*)d_in[4];
    const float* conv_b = (const float*)d_in[5];
    const float* W_x    = (const float*)d_in[6];
    const float* W_dt   = (const float*)d_in[7];
    const float* b_dt   = (const float*)d_in[8];
    const float* A_log  = (const float*)d_in[9];
    const float* Dp     = (const float*)d_in[10];
    const float* W_out  = (const float*)d_in[11];
    float* out = (float*)d_out;

    float *ph, *pxz, *pxc, *pproj, *pdt, *py;
    float *pWtIn, *pWtX, *pWtDt, *pWtOut;
    cudaGetSymbolAddress((void**)&ph,     g_h);
    cudaGetSymbolAddress((void**)&pxz,    g_xz);
    cudaGetSymbolAddress((void**)&pxc,    g_xc);
    cudaGetSymbolAddress((void**)&pproj,  g_proj);
    cudaGetSymbolAddress((void**)&pdt,    g_dt);
    cudaGetSymbolAddress((void**)&py,     g_y);
    cudaGetSymbolAddress((void**)&pWtIn,  g_WtIn);
    cudaGetSymbolAddress((void**)&pWtX,   g_WtX);
    cudaGetSymbolAddress((void**)&pWtDt,  g_WtDt);
    cudaGetSymbolAddress((void**)&pWtOut, g_WtOut);

    cudaFuncSetAttribute(mma_gemm<0>, cudaFuncAttributeMaxDynamicSharedMemorySize, GEMM_SMEM);
    cudaFuncSetAttribute(mma_gemm<1>, cudaFuncAttributeMaxDynamicSharedMemorySize, GEMM_SMEM);
    cudaFuncSetAttribute(mma_gemm<2>, cudaFuncAttributeMaxDynamicSharedMemorySize, GEMM_SMEM);

    dim3 tb(32, 8);

    // launch 0: transpose W_in
    transpose_win_kernel<<<dim3(96, 24), tb>>>(W_in);
    // launch 1: LayerNorm
    ln_kernel<<<NROWS, 256>>>(x, gamma, beta);
    // launch 2: remaining transposes (fused)
    transpose_rest_kernel<<<1392, tb>>>(W_x, W_dt, W_out);

    // launch 3 (ncu capture slot): xz = h @ W_in
    mma_gemm<0><<<dim3((2 * DI) / 128, NROWS / 128), 256, GEMM_SMEM>>>(
        ph, DM, pWtIn, DM, pxz, 2 * DI, 2 * DI, DM, nullptr, nullptr, 0);

    // launch 4: depthwise conv + silu
    conv_silu_kernel<<<(NROWS * DI + 255) / 256, 256>>>(conv_w, conv_b);

    // launch 5: proj = xc @ W_x
    mma_gemm<0><<<dim3(1, NROWS / 128), 256, GEMM_SMEM>>>(
        pxc, DI, pWtX, DI, pproj, PROJW, PROJW, DI, nullptr, nullptr, 0);

    // launch 6: dt = softplus(proj[:, :48] @ W_dt + b_dt)
    mma_gemm<1><<<dim3(DI / 128, NROWS / 128), 256, GEMM_SMEM>>>(
        pproj, PROJW, pWtDt, DTR, pdt, DI, DI, DTR, b_dt, nullptr, 0);

    // launch 7: selective scan + D skip + silu(z) gate
    scan_kernel<<<dim3(DI / 16, NB), 256>>>(A_log, Dp);

    // launch 8: out = x + y @ W_out
    mma_gemm<2><<<dim3(DM / 128, NROWS / 128), 256, GEMM_SMEM>>>(
        py, DI, pWtOut, DI, out, DM, DM, DI, nullptr, x, DM);
}

// round 15
// speedup vs baseline: 3.7163x; 1.0463x over previous
#include <cuda_runtime.h>
#include <math.h>
#include <stdint.h>

#define L_SEQ 2048
#define NB 2
#define DM 768
#define DI 1536
#define DS 16
#define DTR 48
#define NROWS (NB * L_SEQ)          // 4096
#define PROJW (DTR + 2 * DS)        // 80
#define KSPLIT6 6

// ---------------- scratch (static device globals, no allocation) ----------------
__device__ float g_h[(size_t)NROWS * DM];
__device__ float g_xz[(size_t)NROWS * 2 * DI];
__device__ float g_xc[(size_t)NROWS * DI];
__device__ float g_proj[(size_t)NROWS * PROJW];
__device__ float g_projP[(size_t)KSPLIT6 * NROWS * PROJW];  // split-K partials
__device__ float g_dt[(size_t)NROWS * DI];
__device__ float g_y[(size_t)NROWS * DI];
// transposed weights (K-major B operands: Bt[n][k])
__device__ float g_WtIn[(size_t)(2 * DI) * DM];
__device__ float g_WtX[(size_t)PROJW * DI];
__device__ float g_WtDt[(size_t)DI * DTR];
__device__ float g_WtOut[(size_t)DM * DI];

__device__ __forceinline__ uint32_t smem_u32(const void* p) {
    uint32_t a;
    asm("{ .reg .u64 t; cvta.to.shared.u64 t, %1; cvt.u32.u64 %0, t; }" : "=r"(a) : "l"(p));
    return a;
}

// ---------------- LayerNorm ----------------
__global__ __launch_bounds__(256) void ln_kernel(const float* __restrict__ x,
                                                 const float* __restrict__ gamma,
                                                 const float* __restrict__ beta) {
    int row = blockIdx.x;
    const float* xr = x + (size_t)row * DM;
    float sum = 0.f, sq = 0.f;
    for (int i = threadIdx.x; i < DM; i += 256) {
        float v = xr[i];
        sum += v;
        sq  += v * v;
    }
    __shared__ float sh[2][8];
    #pragma unroll
    for (int o = 16; o; o >>= 1) {
        sum += __shfl_xor_sync(0xffffffffu, sum, o);
        sq  += __shfl_xor_sync(0xffffffffu, sq, o);
    }
    int w = threadIdx.x >> 5, lane = threadIdx.x & 31;
    if (lane == 0) { sh[0][w] = sum; sh[1][w] = sq; }
    __syncthreads();
    if (threadIdx.x < 32) {
        sum = (lane < 8) ? sh[0][lane] : 0.f;
        sq  = (lane < 8) ? sh[1][lane] : 0.f;
        #pragma unroll
        for (int o = 4; o; o >>= 1) {
            sum += __shfl_xor_sync(0xffffffffu, sum, o);
            sq  += __shfl_xor_sync(0xffffffffu, sq, o);
        }
        if (lane == 0) { sh[0][0] = sum; sh[1][0] = sq; }
    }
    __syncthreads();
    float mu  = sh[0][0] * (1.f / DM);
    float var = sh[1][0] * (1.f / DM) - mu * mu;
    float inv = rsqrtf(var + 1e-5f);
    for (int i = threadIdx.x; i < DM; i += 256)
        g_h[(size_t)row * DM + i] = (xr[i] - mu) * inv * gamma[i] + beta[i];
}

// ---------------- Transpose tile body ----------------
__device__ __forceinline__ void transpose_tile(const float* __restrict__ in,
                                               float* __restrict__ out,
                                               int R, int C, int bx, int by) {
    __shared__ float t[32][33];
    int c0 = bx * 32, r0 = by * 32;
    #pragma unroll
    for (int i = 0; i < 32; i += 8) {
        int x = c0 + threadIdx.x, y = r0 + threadIdx.y + i;
        if (x < C && y < R) t[threadIdx.y + i][threadIdx.x] = in[(size_t)y * C + x];
    }
    __syncthreads();
    #pragma unroll
    for (int i = 0; i < 32; i += 8) {
        int x = r0 + threadIdx.x, y = c0 + threadIdx.y + i;
        if (x < R && y < C) out[(size_t)y * R + x] = t[threadIdx.x][threadIdx.y + i];
    }
}

__global__ __launch_bounds__(256) void transpose_win_kernel(const float* __restrict__ W_in) {
    transpose_tile(W_in, g_WtIn, DM, 2 * DI, blockIdx.x, blockIdx.y);
}

__global__ __launch_bounds__(256) void transpose_rest_kernel(const float* __restrict__ Wx,
                                                             const float* __restrict__ Wdt,
                                                             const float* __restrict__ Wout) {
    int t = blockIdx.x;
    if (t < 144) {
        transpose_tile(Wx, g_WtX, DI, PROJW, t % 3, t / 3);
    } else if (t < 240) {
        t -= 144;
        transpose_tile(Wdt, g_WtDt, DTR, DI, t % 48, t / 48);
    } else {
        t -= 240;
        transpose_tile(Wout, g_WtOut, DI, DM, t % 24, t / 24);
    }
}

// ---------------- tf32 mma.sync GEMM: C[M,N] = A[M,K] @ Bt[N,K]^T -------------
// ldmatrix fragment loads; optional split-K over blockIdx.z.
#define GEMM_SMEM (2 * 4608 * 2 * 4)   // 73728 bytes
#define SPITCH 36
#define BUFB (128 * SPITCH * 4)        // bytes per buffer per operand

template <int EPI>
__global__ __launch_bounds__(256, 2) void mma_gemm(
    const float* __restrict__ A, int lda,
    const float* __restrict__ Bt, int ldb,
    float* __restrict__ C, int ldc,
    int N, int K,
    const float* __restrict__ bias,
    const float* __restrict__ res, int ldres,
    int ksplit, size_t zstride)
{
    extern __shared__ float sm[];
    float* Asm = sm;
    float* Bsm = sm + 2 * 128 * SPITCH;

    const int tid  = threadIdx.x;
    const int lane = tid & 31;
    const int wid  = tid >> 5;
    const int wm   = (wid & 1) * 64;
    const int wn   = (wid >> 1) * 32;
    const int m0   = blockIdx.y * 128;
    const int n0   = blockIdx.x * 128;

    // split-K slice
    const int koff = blockIdx.z * ksplit;
    int Kloc = K - koff; if (Kloc > ksplit) Kloc = ksplit;
    A  += koff;
    Bt += koff;
    C  += blockIdx.z * zstride;

    float acc[4][4][4];
    #pragma unroll
    for (int i = 0; i < 4; i++)
        #pragma unroll
        for (int j = 0; j < 4; j++)
            #pragma unroll
            for (int q = 0; q < 4; q++) acc[i][j][q] = 0.f;

    const int NC = (Kloc + 31) >> 5;

    auto load_chunk = [&](int c) {
        const int k0 = c << 5;
        int kw = Kloc - k0; if (kw > 32) kw = 32;
        float* Ab = Asm + (c & 1) * 128 * SPITCH;
        float* Bb = Bsm + (c & 1) * 128 * SPITCH;
        #pragma unroll
        for (int it = 0; it < 4; ++it) {
            int v = tid + it * 256;
            int r = v >> 3, s = v & 7;
            {
                int sz = (s * 4 < kw) ? 16 : 0;
                const float* src = sz ? (A + (size_t)(m0 + r) * lda + k0 + s * 4) : A;
                uint32_t dst = smem_u32(Ab + r * SPITCH + s * 4);
                asm volatile("cp.async.cg.shared.global [%0], [%1], 16, %2;"
                             :: "r"(dst), "l"(src), "r"(sz) : "memory");
            }
            {
                int n = n0 + r;
                int sz = (n < N && s * 4 < kw) ? 16 : 0;
                const float* src = sz ? (Bt + (size_t)n * ldb + k0 + s * 4) : Bt;
                uint32_t dst = smem_u32(Bb + r * SPITCH + s * 4);
                asm volatile("cp.async.cg.shared.global [%0], [%1], 16, %2;"
                             :: "r"(dst), "l"(src), "r"(sz) : "memory");
            }
        }
        asm volatile("cp.async.commit_group;" ::: "memory");
    };

    // ldmatrix per-thread base addresses (byte units, smem space)
    // A x4: matrices {rows 0-7,k0-3},{rows 8-15,k0-3},{rows 0-7,k4-7},{rows 8-15,k4-7}
    const uint32_t aBase = smem_u32(Asm) +
        ((uint32_t)((wm + (lane & 15)) * SPITCH + ((lane >> 4) << 2)) << 2);
    // B x4 (covers ni pair): {n 0-7,k0-3},{n 0-7,k4-7},{n 8-15,k0-3},{n 8-15,k4-7}
    const uint32_t bBase = smem_u32(Bsm) +
        ((uint32_t)((wn + (lane & 7) + ((lane >> 4) << 3)) * SPITCH +
                    (((lane >> 3) & 1) << 2)) << 2);

    load_chunk(0);
    for (int c = 0; c < NC; ++c) {
        if (c + 1 < NC) {
            load_chunk(c + 1);
            asm volatile("cp.async.wait_group 1;" ::: "memory");
        } else {
            asm volatile("cp.async.wait_group 0;" ::: "memory");
        }
        __syncthreads();

        const uint32_t aB = aBase + (c & 1) * BUFB;
        const uint32_t bB = bBase + (c & 1) * BUFB;
        #pragma unroll
        for (int kk = 0; kk < 4; ++kk) {
            uint32_t af[4][4], bf[4][2];
            #pragma unroll
            for (int mi = 0; mi < 4; ++mi) {
                uint32_t addr = aB + mi * (16 * SPITCH * 4) + kk * 32;
                asm volatile(
                    "ldmatrix.sync.aligned.m8n8.x4.shared.b16 {%0,%1,%2,%3}, [%4];"
                    : "=r"(af[mi][0]), "=r"(af[mi][1]), "=r"(af[mi][2]), "=r"(af[mi][3])
                    : "r"(addr));
            }
            #pragma unroll
            for (int j = 0; j < 2; ++j) {
                uint32_t addr = bB + j * (16 * SPITCH * 4) + kk * 32;
                asm volatile(
                    "ldmatrix.sync.aligned.m8n8.x4.shared.b16 {%0,%1,%2,%3}, [%4];"
                    : "=r"(bf[2 * j][0]), "=r"(bf[2 * j][1]),
                      "=r"(bf[2 * j + 1][0]), "=r"(bf[2 * j + 1][1])
                    : "r"(addr));
            }
            #pragma unroll
            for (int mi = 0; mi < 4; ++mi)
                #pragma unroll
                for (int ni = 0; ni < 4; ++ni) {
                    asm volatile(
                        "mma.sync.aligned.m16n8k8.row.col.f32.tf32.tf32.f32 "
                        "{%0,%1,%2,%3}, {%4,%5,%6,%7}, {%8,%9}, {%0,%1,%2,%3};"
                        : "+f"(acc[mi][ni][0]), "+f"(acc[mi][ni][1]),
                          "+f"(acc[mi][ni][2]), "+f"(acc[mi][ni][3])
                        : "r"(af[mi][0]), "r"(af[mi][1]), "r"(af[mi][2]), "r"(af[mi][3]),
                          "r"(bf[ni][0]), "r"(bf[ni][1]));
                }
        }
        __syncthreads();
    }

    #pragma unroll
    for (int mi = 0; mi < 4; ++mi) {
        #pragma unroll
        for (int ni = 0; ni < 4; ++ni) {
            int row = m0 + wm + mi * 16 + (lane >> 2);
            int col = n0 + wn + ni * 8 + 2 * (lane & 3);
            if (col < N) {
                #pragma unroll
                for (int h = 0; h < 2; ++h) {
                    int r = row + h * 8;
                    float v0 = acc[mi][ni][h * 2 + 0];
                    float v1 = acc[mi][ni][h * 2 + 1];
                    if (EPI == 1) {
                        v0 += bias[col];
                        v1 += bias[col + 1];
                        v0 = (v0 > 20.f) ? v0 : log1pf(__expf(v0));
                        v1 = (v1 > 20.f) ? v1 : log1pf(__expf(v1));
                    }
                    if (EPI == 2) {
                        const float2 rr = *(const float2*)&res[(size_t)r * ldres + col];
                        v0 += rr.x; v1 += rr.y;
                    }
                    float2 o = make_float2(v0, v1);
                    *(float2*)&C[(size_t)r * ldc + col] = o;
                }
            }
        }
    }
}

// ---------------- split-K partial reduction (6 slabs -> g_proj) ----------------
__global__ __launch_bounds__(256) void reduce6_kernel() {
    int i = blockIdx.x * 256 + threadIdx.x;
    const size_t SZ = (size_t)NROWS * PROJW;
    if (i < (int)SZ) {
        float s = 0.f;
        #pragma unroll
        for (int z = 0; z < KSPLIT6; ++z) s += g_projP[(size_t)z * SZ + i];
        g_proj[i] = s;
    }
}

// ---------------- Depthwise causal conv(4) + SiLU ----------------
__global__ __launch_bounds__(256) void conv_silu_kernel(const float* __restrict__ cw,
                                                        const float* __restrict__ cb) {
    int idx = blockIdx.x * blockDim.x + threadIdx.x;
    if (idx >= NROWS * DI) return;
    int d = idx % DI;
    int r = idx / DI;
    int l = r % L_SEQ;
    int b = r / L_SEQ;
    float acc = cb[d];
    #pragma unroll
    for (int k = 0; k < 4; k++) {
        int ll = l + k - 3;
        if (ll >= 0)
            acc = fmaf(g_xz[(size_t)(b * L_SEQ + ll) * (2 * DI) + d], cw[d * 4 + k], acc);
    }
    g_xc[idx] = acc / (1.f + __expf(-acc));
}

// ---------------- Selective scan (pipelined, exp hoisted off critical path) ---
#define SCAN_U 8
__global__ __launch_bounds__(256) void scan_kernel(const float* __restrict__ A_log,
                                                   const float* __restrict__ Dp) {
    int s    = threadIdx.x & 15;
    int dloc = threadIdx.x >> 4;
    int d    = blockIdx.x * 16 + dloc;
    int b    = blockIdx.y;

    float A  = -__expf(A_log[d * DS + s]);
    float Dv = Dp[d];
    float h  = 0.f;

    const float* pdt = g_dt   + (size_t)(b * L_SEQ) * DI + d;
    const float* pxc = g_xc   + (size_t)(b * L_SEQ) * DI + d;
    const float* pz  = g_xz   + (size_t)(b * L_SEQ) * (2 * DI) + DI + d;
    const float* pB  = g_proj + (size_t)(b * L_SEQ) * PROJW + DTR + s;
    const float* pC  = pB + DS;
    float*       py  = g_y    + (size_t)(b * L_SEQ) * DI + d;

    for (int l0 = 0; l0 < L_SEQ; l0 += SCAN_U) {
        float dA[SCAN_U], bx[SCAN_U], Cv[SCAN_U], zv[SCAN_U], xv[SCAN_U];
        #pragma unroll
        for (int u = 0; u < SCAN_U; ++u) {
            int l = l0 + u;
            float dtv = __ldg(pdt + (size_t)l * DI);
            xv[u]  = __ldg(pxc + (size_t)l * DI);
            float Bv = __ldg(pB  + (size_t)l * PROJW);
            Cv[u]  = __ldg(pC  + (size_t)l * PROJW);
            zv[u]  = __ldg(pz  + (size_t)l * (2 * DI));
            dA[u]  = __expf(dtv * A);
            bx[u]  = dtv * xv[u] * Bv;
        }
        #pragma unroll
        for (int u = 0; u < SCAN_U; ++u) {
            h = fmaf(h, dA[u], bx[u]);
            float part = h * Cv[u];
            part += __shfl_xor_sync(0xffffffffu, part, 8);
            part += __shfl_xor_sync(0xffffffffu, part, 4);
            part += __shfl_xor_sync(0xffffffffu, part, 2);
            part += __shfl_xor_sync(0xffffffffu, part, 1);
            if (s == 0) {
                float sig = 1.f / (1.f + __expf(-zv[u]));
                py[(size_t)(l0 + u) * DI] = (part + xv[u] * Dv) * (zv[u] * sig);
            }
        }
    }
}

// ---------------- launch ----------------
extern "C" void kernel_launch(void* const* d_in, const int* in_sizes, int n_in,
                              void* d_out, int out_size) {
    const float* x      = (const float*)d_in[0];
    const float* gamma  = (const float*)d_in[1];
    const float* beta   = (const float*)d_in[2];
    const float* W_in   = (const float*)d_in[3];
    const float* conv_w = (const float*)d_in[4];
    const float* conv_b = (const float*)d_in[5];
    const float* W_x    = (const float*)d_in[6];
    const float* W_dt   = (const float*)d_in[7];
    const float* b_dt   = (const float*)d_in[8];
    const float* A_log  = (const float*)d_in[9];
    const float* Dp     = (const float*)d_in[10];
    const float* W_out  = (const float*)d_in[11];
    float* out = (float*)d_out;

    float *ph, *pxz, *pxc, *pproj, *pprojP, *pdt, *py;
    float *pWtIn, *pWtX, *pWtDt, *pWtOut;
    cudaGetSymbolAddress((void**)&ph,     g_h);
    cudaGetSymbolAddress((void**)&pxz,    g_xz);
    cudaGetSymbolAddress((void**)&pxc,    g_xc);
    cudaGetSymbolAddress((void**)&pproj,  g_proj);
    cudaGetSymbolAddress((void**)&pprojP, g_projP);
    cudaGetSymbolAddress((void**)&pdt,    g_dt);
    cudaGetSymbolAddress((void**)&py,     g_y);
    cudaGetSymbolAddress((void**)&pWtIn,  g_WtIn);
    cudaGetSymbolAddress((void**)&pWtX,   g_WtX);
    cudaGetSymbolAddress((void**)&pWtDt,  g_WtDt);
    cudaGetSymbolAddress((void**)&pWtOut, g_WtOut);

    cudaFuncSetAttribute(mma_gemm<0>, cudaFuncAttributeMaxDynamicSharedMemorySize, GEMM_SMEM);
    cudaFuncSetAttribute(mma_gemm<1>, cudaFuncAttributeMaxDynamicSharedMemorySize, GEMM_SMEM);
    cudaFuncSetAttribute(mma_gemm<2>, cudaFuncAttributeMaxDynamicSharedMemorySize, GEMM_SMEM);

    dim3 tb(32, 8);

    // launch 0: transpose W_in
    transpose_win_kernel<<<dim3(96, 24), tb>>>(W_in);
    // launch 1: LayerNorm
    ln_kernel<<<NROWS, 256>>>(x, gamma, beta);
    // launch 2: remaining transposes (fused)
    transpose_rest_kernel<<<1392, tb>>>(W_x, W_dt, W_out);

    // launch 3 (ncu capture slot): xz = h @ W_in
    mma_gemm<0><<<dim3((2 * DI) / 128, NROWS / 128, 1), 256, GEMM_SMEM>>>(
        ph, DM, pWtIn, DM, pxz, 2 * DI, 2 * DI, DM, nullptr, nullptr, 0, DM, 0);

    // launch 4: depthwise conv + silu
    conv_silu_kernel<<<(NROWS * DI + 255) / 256, 256>>>(conv_w, conv_b);

    // launch 5: proj partials = xc @ W_x (split-K x6)
    mma_gemm<0><<<dim3(1, NROWS / 128, KSPLIT6), 256, GEMM_SMEM>>>(
        pxc, DI, pWtX, DI, pprojP, PROJW, PROJW, DI, nullptr, nullptr, 0,
        DI / KSPLIT6, (size_t)NROWS * PROJW);

    // launch 6: reduce proj partials
    reduce6_kernel<<<(NROWS * PROJW + 255) / 256, 256>>>();

    // launch 7: dt = softplus(proj[:, :48] @ W_dt + b_dt)
    mma_gemm<1><<<dim3(DI / 128, NROWS / 128, 1), 256, GEMM_SMEM>>>(
        pproj, PROJW, pWtDt, DTR, pdt, DI, DI, DTR, b_dt, nullptr, 0, DTR, 0);

    // launch 8: selective scan + D skip + silu(z) gate
    scan_kernel<<<dim3(DI / 16, NB), 256>>>(A_log, Dp);

    // launch 9: out = x + y @ W_out
    mma_gemm<2><<<dim3(DM / 128, NROWS / 128, 1), 256, GEMM_SMEM>>>(
        py, DI, pWtOut, DI, out, DM, DM, DI, nullptr, x, DM, DI, 0);
}